// round 16
// baseline (speedup 1.0000x reference)
#include <cuda_runtime.h>
#include <cuda_fp16.h>
#include <stdint.h>
#include <math.h>

#define SEQ   2048
#define BATCH 2
#define NH    16
#define DKV   64
#define DM    1024
#define MTOT  (BATCH*SEQ)
#define LOG2E 1.44269504f

// ---- static device scratch (no allocs) ----
__device__ __align__(16) __half g_xh[MTOT*DM], g_xl[MTOT*DM];
__device__ __align__(16) __half g_wth[4][DM*DM], g_wtl[4][DM*DM];
__device__ __align__(16) __half g_qh[BATCH*NH*SEQ*DKV], g_ql[BATCH*NH*SEQ*DKV];
__device__ __align__(16) __half g_kh[BATCH*NH*SEQ*DKV], g_kl[BATCH*NH*SEQ*DKV];
__device__ __align__(16) __half g_vh[BATCH*NH*SEQ*DKV];
__device__ __align__(16) __half g_ch[MTOT*DM];

// ---- helpers ----
__device__ __forceinline__ uint32_t smem_u32(const void* p) {
    uint32_t a;
    asm("{ .reg .u64 t; cvta.to.shared.u64 t, %1; cvt.u32.u64 %0, t; }" : "=r"(a) : "l"(p));
    return a;
}
__device__ __forceinline__ void hmma(float* d, const uint32_t* a, uint32_t b0, uint32_t b1) {
    asm volatile("mma.sync.aligned.m16n8k16.row.col.f32.f16.f16.f32 "
        "{%0,%1,%2,%3}, {%4,%5,%6,%7}, {%8,%9}, {%0,%1,%2,%3};"
        : "+f"(d[0]), "+f"(d[1]), "+f"(d[2]), "+f"(d[3])
        : "r"(a[0]), "r"(a[1]), "r"(a[2]), "r"(a[3]), "r"(b0), "r"(b1));
}
__device__ __forceinline__ void ldsm4(uint32_t* r, uint32_t addr) {
    asm volatile("ldmatrix.sync.aligned.m8n8.x4.shared.b16 {%0,%1,%2,%3}, [%4];"
        : "=r"(r[0]), "=r"(r[1]), "=r"(r[2]), "=r"(r[3]) : "r"(addr));
}
__device__ __forceinline__ void ldsm4t(uint32_t* r, uint32_t addr) {
    asm volatile("ldmatrix.sync.aligned.m8n8.x4.trans.shared.b16 {%0,%1,%2,%3}, [%4];"
        : "=r"(r[0]), "=r"(r[1]), "=r"(r[2]), "=r"(r[3]) : "r"(addr));
}
__device__ __forceinline__ void cpa(uint32_t dst, const void* src) {
    asm volatile("cp.async.cg.shared.global [%0], [%1], 16;" :: "r"(dst), "l"(src));
}
#define CP_COMMIT() asm volatile("cp.async.commit_group;" ::: "memory")
#define CP_WAIT1()  asm volatile("cp.async.wait_group 1;" ::: "memory")
#define CP_WAIT0()  asm volatile("cp.async.wait_group 0;" ::: "memory")

__device__ __forceinline__ void split2(float v, __half& hi, __half& lo) {
    hi = __float2half_rn(v);
    lo = __float2half_rn(v - __half2float(hi));
}
__device__ __forceinline__ uint32_t packh2(float a, float b) {
    __half2 h = __floats2half2_rn(a, b);
    return *(uint32_t*)&h;
}

// ---- prep ----
__global__ __launch_bounds__(256) void split_x_kernel(const float* __restrict__ x) {
    int i = (blockIdx.x * 256 + threadIdx.x) * 4;
    float4 v = *(const float4*)(x + i);
    __half h0,h1,h2,h3,l0,l1,l2,l3;
    split2(v.x,h0,l0); split2(v.y,h1,l1); split2(v.z,h2,l2); split2(v.w,h3,l3);
    __half2 hh[2] = { __halves2half2(h0,h1), __halves2half2(h2,h3) };
    __half2 ll[2] = { __halves2half2(l0,l1), __halves2half2(l2,l3) };
    *(uint2*)(g_xh + i) = *(uint2*)hh;
    *(uint2*)(g_xl + i) = *(uint2*)ll;
}
__global__ __launch_bounds__(256) void wsplit2_kernel(const float* __restrict__ Wa,
                                                      const float* __restrict__ Wb, int widx0) {
    __shared__ float t[32][33];
    const float* W = blockIdx.z ? Wb : Wa;
    int widx = widx0 + blockIdx.z;
    int n0 = blockIdx.x * 32, k0 = blockIdx.y * 32;
    int tx = threadIdx.x, ty = threadIdx.y;
    #pragma unroll
    for (int i = 0; i < 32; i += 8)
        t[ty + i][tx] = W[(size_t)(k0 + ty + i) * DM + n0 + tx];
    __syncthreads();
    #pragma unroll
    for (int i = 0; i < 32; i += 8) {
        int n = n0 + ty + i, k = k0 + tx;
        __half hi, lo; split2(t[tx][ty + i], hi, lo);
        g_wth[widx][(size_t)n * DM + k] = hi;
        g_wtl[widx][(size_t)n * DM + k] = lo;
    }
}

// ---- split-fp16 MMA GEMM (128x128, 2 CTAs/SM, 3-stage, warp-staggered phases) ----
#define GS_BUF  32768
#define G_SMEM  (3*GS_BUF)
#define GS3_BUF 24576
#define G3_SMEM (3*GS3_BUF)
#define NCH     32

__device__ __forceinline__ void g_issue(uint32_t smb, const __half* const* mats,
                                        int c, int tid) {
    if (c < NCH) {
        uint32_t bufb = smb + (c % 3) * GS_BUF;
        #pragma unroll
        for (int i = 0; i < 8; i++) {
            int u = tid + i * 256;
            int mat = u >> 9, rem = u & 511, row = rem >> 2, seg = rem & 3;
            const void* src = mats[mat] + (size_t)row * DM + c * 32 + seg * 8;
            uint32_t dst = bufb + mat * 8192 + row * 64 + ((seg ^ ((row >> 1) & 3)) << 4);
            cpa(dst, src);
        }
    }
    CP_COMMIT();
}

// 3-term: acc += Ah*Bh + Ah*Bl + Al*Bh    (mats = {Ah, Al, Bh, Bl})
// Warp-staggered ks order: even warps ks 0,1; odd warps ks 1,0 — so at any
// instant ~half the warps are in ldsm phase and half in hmma phase.
__device__ __forceinline__ void g_mainloop(uint32_t smb, const __half* const* mats,
                                           float acc[2][8][4], int tid) {
    const int lane = tid & 31, wid = tid >> 5;
    const int wm = wid >> 1, wn = wid & 1;
    const int rsel = (lane & 7) + ((lane >> 3) & 1) * 8;
    const int chalf = lane >> 4;
    const int kflip = wid & 1;

    g_issue(smb, mats, 0, tid);
    g_issue(smb, mats, 1, tid);
    for (int c = 0; c < NCH; c++) {
        CP_WAIT1();
        __syncthreads();
        g_issue(smb, mats, c + 2, tid);
        uint32_t ab = smb + (c % 3) * GS_BUF;
        #pragma unroll
        for (int ksx = 0; ksx < 2; ksx++) {
            int ks = ksx ^ kflip;
            int sseg = 2 * ks + chalf;
            uint32_t ah[2][4], al_[2][4];
            #pragma unroll
            for (int mi = 0; mi < 2; mi++) {
                int row = wm * 32 + mi * 16 + rsel;
                uint32_t off = row * 64 + ((sseg ^ ((row >> 1) & 3)) << 4);
                ldsm4(ah[mi], ab + off);
                ldsm4(al_[mi], ab + 8192 + off);
            }
            #pragma unroll
            for (int pp = 0; pp < 2; pp++) {
                uint32_t bh_[2][4], bl_[2][4];
                #pragma unroll
                for (int p = 0; p < 2; p++) {
                    int row = wn * 64 + (pp * 2 + p) * 16 + rsel;
                    uint32_t off = row * 64 + ((sseg ^ ((row >> 1) & 3)) << 4);
                    ldsm4(bh_[p], ab + 16384 + off);
                    ldsm4(bl_[p], ab + 24576 + off);
                }
                #pragma unroll
                for (int p = 0; p < 2; p++)
                    #pragma unroll
                    for (int mi = 0; mi < 2; mi++) {
                        int nq = 2 * (2 * pp + p);
                        hmma(acc[mi][nq],     ah[mi], bh_[p][0], bh_[p][2]);
                        hmma(acc[mi][nq + 1], ah[mi], bh_[p][1], bh_[p][3]);
                    }
                #pragma unroll
                for (int p = 0; p < 2; p++)
                    #pragma unroll
                    for (int mi = 0; mi < 2; mi++) {
                        int nq = 2 * (2 * pp + p);
                        hmma(acc[mi][nq],     ah[mi], bl_[p][0], bl_[p][2]);
                        hmma(acc[mi][nq + 1], ah[mi], bl_[p][1], bl_[p][3]);
                    }
                #pragma unroll
                for (int p = 0; p < 2; p++)
                    #pragma unroll
                    for (int mi = 0; mi < 2; mi++) {
                        int nq = 2 * (2 * pp + p);
                        hmma(acc[mi][nq],     al_[mi], bh_[p][0], bh_[p][2]);
                        hmma(acc[mi][nq + 1], al_[mi], bh_[p][1], bh_[p][3]);
                    }
            }
        }
    }
}

__device__ __forceinline__ void g_issue3(uint32_t smb, const __half* const* mats,
                                         int c, int tid) {
    if (c < NCH) {
        uint32_t bufb = smb + (c % 3) * GS3_BUF;
        #pragma unroll
        for (int i = 0; i < 6; i++) {
            int u = tid + i * 256;
            int mat = u >> 9, rem = u & 511, row = rem >> 2, seg = rem & 3;
            const void* src = mats[mat] + (size_t)row * DM + c * 32 + seg * 8;
            uint32_t dst = bufb + mat * 8192 + row * 64 + ((seg ^ ((row >> 1) & 3)) << 4);
            cpa(dst, src);
        }
    }
    CP_COMMIT();
}

// 2-term: acc += A*Bh + A*Bl    (mats = {A, Bh, Bl}), warp-staggered
__device__ __forceinline__ void g_mainloop3(uint32_t smb, const __half* const* mats,
                                            float acc[2][8][4], int tid) {
    const int lane = tid & 31, wid = tid >> 5;
    const int wm = wid >> 1, wn = wid & 1;
    const int rsel = (lane & 7) + ((lane >> 3) & 1) * 8;
    const int chalf = lane >> 4;
    const int kflip = wid & 1;

    g_issue3(smb, mats, 0, tid);
    g_issue3(smb, mats, 1, tid);
    for (int c = 0; c < NCH; c++) {
        CP_WAIT1();
        __syncthreads();
        g_issue3(smb, mats, c + 2, tid);
        uint32_t ab = smb + (c % 3) * GS3_BUF;
        #pragma unroll
        for (int ksx = 0; ksx < 2; ksx++) {
            int ks = ksx ^ kflip;
            int sseg = 2 * ks + chalf;
            uint32_t ah[2][4];
            #pragma unroll
            for (int mi = 0; mi < 2; mi++) {
                int row = wm * 32 + mi * 16 + rsel;
                uint32_t off = row * 64 + ((sseg ^ ((row >> 1) & 3)) << 4);
                ldsm4(ah[mi], ab + off);
            }
            #pragma unroll
            for (int pp = 0; pp < 2; pp++) {
                uint32_t bh_[2][4], bl_[2][4];
                #pragma unroll
                for (int p = 0; p < 2; p++) {
                    int row = wn * 64 + (pp * 2 + p) * 16 + rsel;
                    uint32_t off = row * 64 + ((sseg ^ ((row >> 1) & 3)) << 4);
                    ldsm4(bh_[p], ab + 8192 + off);
                    ldsm4(bl_[p], ab + 16384 + off);
                }
                #pragma unroll
                for (int p = 0; p < 2; p++)
                    #pragma unroll
                    for (int mi = 0; mi < 2; mi++) {
                        int nq = 2 * (2 * pp + p);
                        hmma(acc[mi][nq],     ah[mi], bh_[p][0], bh_[p][2]);
                        hmma(acc[mi][nq + 1], ah[mi], bh_[p][1], bh_[p][3]);
                    }
                #pragma unroll
                for (int p = 0; p < 2; p++)
                    #pragma unroll
                    for (int mi = 0; mi < 2; mi++) {
                        int nq = 2 * (2 * pp + p);
                        hmma(acc[mi][nq],     ah[mi], bl_[p][0], bl_[p][2]);
                        hmma(acc[mi][nq + 1], ah[mi], bl_[p][1], bl_[p][3]);
                    }
            }
        }
    }
}

// Fused QKV projection: z = 0(Q, hi/lo), 1(K, hi/lo), 2(V, hi-only)
__global__ __launch_bounds__(256, 2) void qkv_gemm() {
    extern __shared__ char smg[];
    uint32_t smb = smem_u32(smg);
    const int tid = threadIdx.x, lane = tid & 31, wid = tid >> 5;
    const int m0 = blockIdx.y * 128, n0 = blockIdx.x * 128, z = blockIdx.z;
    const int wm = wid >> 1, wn = wid & 1;

    const __half* mats[4] = { g_xh + (size_t)m0 * DM, g_xl + (size_t)m0 * DM,
                              g_wth[z] + (size_t)n0 * DM, g_wtl[z] + (size_t)n0 * DM };
    float acc[2][8][4];
    #pragma unroll
    for (int i = 0; i < 2; i++)
        #pragma unroll
        for (int j = 0; j < 8; j++)
            #pragma unroll
            for (int e = 0; e < 4; e++) acc[i][j][e] = 0.f;

    g_mainloop(smb, mats, acc, tid);

    __half* Oh = (z == 0) ? g_qh : (z == 1) ? g_kh : g_vh;
    __half* Ol = (z == 0) ? g_ql : g_kl;
    const int g = lane >> 2, q2 = (lane & 3) * 2;
    #pragma unroll
    for (int mi = 0; mi < 2; mi++)
        #pragma unroll
        for (int rr = 0; rr < 2; rr++) {
            int m = m0 + wm * 32 + mi * 16 + g + rr * 8;
            int bb = m >> 11, ss = m & (SEQ - 1);
            #pragma unroll
            for (int nj = 0; nj < 8; nj++) {
                float v0 = acc[mi][nj][rr * 2], v1 = acc[mi][nj][rr * 2 + 1];
                int n = n0 + wn * 64 + nj * 8 + q2;
                int hh = n >> 6, dd = n & 63;
                size_t off = (((size_t)(bb * NH + hh)) * SEQ + ss) * DKV + dd;
                __half h0, h1, l0, l1;
                split2(v0, h0, l0); split2(v1, h1, l1);
                __half2 ph = __halves2half2(h0, h1);
                *(uint32_t*)(Oh + off) = *(uint32_t*)&ph;
                if (z < 2) {
                    __half2 pl = __halves2half2(l0, l1);
                    *(uint32_t*)(Ol + off) = *(uint32_t*)&pl;
                }
            }
        }
}

// Output GEMM: out = ctx_hi @ wo, 2-term (wo hi+lo), fp32 row-major
__global__ __launch_bounds__(256, 2) void out_gemm(float* __restrict__ Cf) {
    extern __shared__ char smg[];
    uint32_t smb = smem_u32(smg);
    const int tid = threadIdx.x, lane = tid & 31, wid = tid >> 5;
    const int m0 = blockIdx.y * 128, n0 = blockIdx.x * 128;
    const int wm = wid >> 1, wn = wid & 1;

    const __half* mats[3] = { g_ch + (size_t)m0 * DM,
                              g_wth[3] + (size_t)n0 * DM, g_wtl[3] + (size_t)n0 * DM };
    float acc[2][8][4];
    #pragma unroll
    for (int i = 0; i < 2; i++)
        #pragma unroll
        for (int j = 0; j < 8; j++)
            #pragma unroll
            for (int e = 0; e < 4; e++) acc[i][j][e] = 0.f;

    g_mainloop3(smb, mats, acc, tid);

    const int g = lane >> 2, q2 = (lane & 3) * 2;
    #pragma unroll
    for (int mi = 0; mi < 2; mi++)
        #pragma unroll
        for (int rr = 0; rr < 2; rr++) {
            int m = m0 + wm * 32 + mi * 16 + g + rr * 8;
            #pragma unroll
            for (int nj = 0; nj < 8; nj++) {
                int n = n0 + wn * 64 + nj * 8 + q2;
                *(float2*)(Cf + (size_t)m * DM + n) =
                    make_float2(acc[mi][nj][rr * 2], acc[mi][nj][rr * 2 + 1]);
            }
        }
}

// ---- FA2-style mma.sync flash attention (warp-staggered QK/PV phases) ----
#define AT_QH 0
#define AT_QL 16384
#define AT_KV 32768            /* 2 bufs x 24576 (Kh 8K | Kl 8K | V 8K) */
#define AT_BI 81920
#define AT_SMEM (81920 + 2176*4)

__device__ __forceinline__ void attn_issue(uint32_t smb, const __half* kh, const __half* kl,
                                           const __half* vh, int t, int buf, int tid) {
    #pragma unroll
    for (int i = 0; i < 6; i++) {
        int u = tid + i * 256;
        int mat = u >> 9, rem = u & 511, row = rem >> 3, seg = rem & 7;
        const __half* base = (mat == 0) ? kh : (mat == 1) ? kl : vh;
        const void* src = base + (size_t)(t * 64 + row) * DKV + seg * 8;
        uint32_t dst = smb + AT_KV + buf * 24576 + mat * 8192 + row * 128 + ((seg ^ (row & 7)) << 4);
        cpa(dst, src);
    }
    CP_COMMIT();
}

__global__ __launch_bounds__(256, 2) void attn_mma(const float* __restrict__ rel_emb)
{
    extern __shared__ char smn[];
    uint32_t smb = smem_u32(smn);
    const int tid = threadIdx.x, lane = tid & 31, wid = tid >> 5;
    const int b = blockIdx.z, h = blockIdx.y, q0 = blockIdx.x * 128;
    const size_t hoff = ((size_t)(b * NH + h)) * SEQ * DKV;
    const __half* kh = g_kh + hoff;
    const __half* kl = g_kl + hoff;
    const __half* vh = g_vh + hoff;

    attn_issue(smb, kh, kl, vh, 0, 0, tid);

    #pragma unroll
    for (int i = 0; i < 8; i++) {
        int u = tid + i * 256;
        int mat = u >> 10, rem = u & 1023, row = rem >> 3, seg = rem & 7;
        const uint4* src = (const uint4*)(((mat == 0) ? g_qh : g_ql) + hoff
                             + (size_t)(q0 + row) * DKV + seg * 8);
        *(uint4*)(smn + mat * 16384 + row * 128 + ((seg ^ (row & 7)) << 4)) = *src;
    }
    float* biasS = (float*)(smn + AT_BI);
    for (int j = tid; j < 2175; j += 256) {
        int rel = j - (q0 + 127);
        int n = -rel, ret = 0;
        if (n < 0) { ret = 16; n = -n; }
        int bkt;
        if (n < 8) bkt = n;
        else {
            float t = logf((float)n * 0.125f) / 2.7725887222397812f * 8.0f;
            int v = 8 + (int)t;
            bkt = v < 15 ? v : 15;
        }
        biasS[j] = __ldg(&rel_emb[(ret + bkt) * NH + h]);
    }
    __syncthreads();

    const int rsel = (lane & 7) + ((lane >> 3) & 1) * 8;
    const int chalf = lane >> 4;
    const int qrow = wid * 16 + rsel;
    const int wrot = wid & 3;

    float O[8][4];
    #pragma unroll
    for (int j = 0; j < 8; j++)
        #pragma unroll
        for (int e = 0; e < 4; e++) O[j][e] = 0.f;
    float m0r = -1e30f, m1r = -1e30f, l0 = 0.f, l1 = 0.f;
    const int g = lane >> 2, q2 = (lane & 3) * 2;
    const int qr0 = wid * 16 + g;

    for (int t = 0; t < 32; t++) {
        CP_WAIT0();
        __syncthreads();
        if (t < 31) attn_issue(smb, kh, kl, vh, t + 1, (t + 1) & 1, tid);
        uint32_t kb = smb + AT_KV + (t & 1) * 24576;

        float s[8][4];
        #pragma unroll
        for (int j = 0; j < 8; j++)
            #pragma unroll
            for (int e = 0; e < 4; e++) s[j][e] = 0.f;

        #pragma unroll
        for (int ksx = 0; ksx < 4; ksx++) {
            int ks = (ksx + wrot) & 3;
            int sseg = 2 * ks + chalf;
            uint32_t qfh[4], qfl[4];
            uint32_t qoff = qrow * 128 + ((sseg ^ (qrow & 7)) << 4);
            ldsm4(qfh, smb + AT_QH + qoff);
            ldsm4(qfl, smb + AT_QL + qoff);
            #pragma unroll
            for (int pp = 0; pp < 2; pp++) {
                uint32_t kbh[2][4], kbl[2][4];
                #pragma unroll
                for (int p = 0; p < 2; p++) {
                    int row = (pp * 2 + p) * 16 + rsel;
                    uint32_t off = row * 128 + ((sseg ^ (row & 7)) << 4);
                    ldsm4(kbh[p], kb + off);
                    ldsm4(kbl[p], kb + 8192 + off);
                }
                #pragma unroll
                for (int p = 0; p < 2; p++) {
                    int nq = 2 * (2 * pp + p);
                    hmma(s[nq],     qfh, kbh[p][0], kbh[p][2]);
                    hmma(s[nq + 1], qfh, kbh[p][1], kbh[p][3]);
                }
                #pragma unroll
                for (int p = 0; p < 2; p++) {
                    int nq = 2 * (2 * pp + p);
                    hmma(s[nq],     qfh, kbl[p][0], kbl[p][2]);
                    hmma(s[nq + 1], qfh, kbl[p][1], kbl[p][3]);
                }
                #pragma unroll
                for (int p = 0; p < 2; p++) {
                    int nq = 2 * (2 * pp + p);
                    hmma(s[nq],     qfl, kbh[p][0], kbh[p][2]);
                    hmma(s[nq + 1], qfl, kbh[p][1], kbh[p][3]);
                }
            }
        }

        const float* bp0 = biasS + t * 64 + q2 + 127 - qr0;
        const float* bp1 = bp0 - 8;
        float mx0 = m0r, mx1 = m1r;
        #pragma unroll
        for (int nj = 0; nj < 8; nj++) {
            s[nj][0] += bp0[nj * 8];     s[nj][1] += bp0[nj * 8 + 1];
            s[nj][2] += bp1[nj * 8];     s[nj][3] += bp1[nj * 8 + 1];
            mx0 = fmaxf(mx0, fmaxf(s[nj][0], s[nj][1]));
            mx1 = fmaxf(mx1, fmaxf(s[nj][2], s[nj][3]));
        }
        mx0 = fmaxf(mx0, __shfl_xor_sync(0xffffffffu, mx0, 1));
        mx0 = fmaxf(mx0, __shfl_xor_sync(0xffffffffu, mx0, 2));
        mx1 = fmaxf(mx1, __shfl_xor_sync(0xffffffffu, mx1, 1));
        mx1 = fmaxf(mx1, __shfl_xor_sync(0xffffffffu, mx1, 2));
        float c0 = exp2f((m0r - mx0) * LOG2E);
        float c1 = exp2f((m1r - mx1) * LOG2E);
        m0r = mx0; m1r = mx1;
        float sum0 = 0.f, sum1 = 0.f;
        #pragma unroll
        for (int nj = 0; nj < 8; nj++) {
            s[nj][0] = exp2f((s[nj][0] - mx0) * LOG2E);
            s[nj][1] = exp2f((s[nj][1] - mx0) * LOG2E);
            s[nj][2] = exp2f((s[nj][2] - mx1) * LOG2E);
            s[nj][3] = exp2f((s[nj][3] - mx1) * LOG2E);
            sum0 += s[nj][0] + s[nj][1];
            sum1 += s[nj][2] + s[nj][3];
        }
        sum0 += __shfl_xor_sync(0xffffffffu, sum0, 1);
        sum0 += __shfl_xor_sync(0xffffffffu, sum0, 2);
        sum1 += __shfl_xor_sync(0xffffffffu, sum1, 1);
        sum1 += __shfl_xor_sync(0xffffffffu, sum1, 2);
        l0 = l0 * c0 + sum0;
        l1 = l1 * c1 + sum1;
        #pragma unroll
        for (int nd = 0; nd < 8; nd++) {
            O[nd][0] *= c0; O[nd][1] *= c0; O[nd][2] *= c1; O[nd][3] *= c1;
        }

        #pragma unroll
        for (int kvx = 0; kvx < 4; kvx++) {
            int kv = (kvx + wrot) & 3;
            uint32_t pf[4];
            pf[0] = packh2(s[2*kv][0],   s[2*kv][1]);
            pf[1] = packh2(s[2*kv][2],   s[2*kv][3]);
            pf[2] = packh2(s[2*kv+1][0], s[2*kv+1][1]);
            pf[3] = packh2(s[2*kv+1][2], s[2*kv+1][3]);
            int krow = kv * 16 + rsel;
            #pragma unroll
            for (int ndp = 0; ndp < 4; ndp++) {
                int seg = 2 * ndp + chalf;
                uint32_t off = krow * 128 + ((seg ^ (krow & 7)) << 4);
                uint32_t vb[4];
                ldsm4t(vb, kb + 16384 + off);
                hmma(O[2*ndp],   pf, vb[0], vb[1]);
                hmma(O[2*ndp+1], pf, vb[2], vb[3]);
            }
        }
    }

    float inv0 = 1.0f / l0, inv1 = 1.0f / l1;
    #pragma unroll
    for (int rr = 0; rr < 2; rr++) {
        int q = q0 + wid * 16 + g + rr * 8;
        float inv = rr ? inv1 : inv0;
        size_t base = ((size_t)(b * SEQ + q)) * DM + h * DKV + q2;
        #pragma unroll
        for (int nd = 0; nd < 8; nd++) {
            uint32_t ph = packh2(O[nd][rr * 2] * inv, O[nd][rr * 2 + 1] * inv);
            *(uint32_t*)(g_ch + base + nd * 8) = ph;
        }
    }
}

// ---------------------------------------------------------------------------
extern "C" void kernel_launch(void* const* d_in, const int* in_sizes, int n_in,
                              void* d_out, int out_size)
{
    const float* x   = (const float*)d_in[0];
    const float* wq  = (const float*)d_in[1];
    const float* wk  = (const float*)d_in[2];
    const float* wv  = (const float*)d_in[3];
    const float* wo  = (const float*)d_in[4];
    const float* rel = (const float*)d_in[5];
    float* out = (float*)d_out;

    cudaFuncSetAttribute(qkv_gemm, cudaFuncAttributeMaxDynamicSharedMemorySize, G_SMEM);
    cudaFuncSetAttribute(out_gemm, cudaFuncAttributeMaxDynamicSharedMemorySize, G3_SMEM);
    cudaFuncSetAttribute(attn_mma, cudaFuncAttributeMaxDynamicSharedMemorySize, AT_SMEM);

    split_x_kernel<<<MTOT*DM/1024, 256>>>(x);
    dim3 wg(32, 32, 2), wb(32, 8);
    wsplit2_kernel<<<wg, wb>>>(wq, wk, 0);
    wsplit2_kernel<<<wg, wb>>>(wv, wo, 2);
    qkv_gemm<<<dim3(DM/128, MTOT/128, 3), 256, G_SMEM>>>();
    attn_mma<<<dim3(SEQ/128, NH, BATCH), 256, AT_SMEM>>>(rel);
    out_gemm<<<dim3(DM/128, MTOT/128), 256, G3_SMEM>>>(out);
}

// round 17
// speedup vs baseline: 1.2101x; 1.2101x over previous
#include <cuda_runtime.h>
#include <cuda_fp16.h>
#include <stdint.h>
#include <math.h>

#define SEQ   2048
#define BATCH 2
#define NH    16
#define DKV   64
#define DM    1024
#define MTOT  (BATCH*SEQ)
#define LOG2E 1.44269504f

// ---- static device scratch (no allocs) ----
__device__ __align__(16) __half g_xh[MTOT*DM], g_xl[MTOT*DM];
__device__ __align__(16) __half g_wth[4][DM*DM], g_wtl[4][DM*DM];
__device__ __align__(16) __half g_qh[BATCH*NH*SEQ*DKV], g_ql[BATCH*NH*SEQ*DKV];
__device__ __align__(16) __half g_kh[BATCH*NH*SEQ*DKV], g_kl[BATCH*NH*SEQ*DKV];
__device__ __align__(16) __half g_vh[BATCH*NH*SEQ*DKV];
__device__ __align__(16) __half g_ch[MTOT*DM];

// ---- helpers ----
__device__ __forceinline__ uint32_t smem_u32(const void* p) {
    uint32_t a;
    asm("{ .reg .u64 t; cvta.to.shared.u64 t, %1; cvt.u32.u64 %0, t; }" : "=r"(a) : "l"(p));
    return a;
}
__device__ __forceinline__ void hmma(float* d, const uint32_t* a, uint32_t b0, uint32_t b1) {
    asm volatile("mma.sync.aligned.m16n8k16.row.col.f32.f16.f16.f32 "
        "{%0,%1,%2,%3}, {%4,%5,%6,%7}, {%8,%9}, {%0,%1,%2,%3};"
        : "+f"(d[0]), "+f"(d[1]), "+f"(d[2]), "+f"(d[3])
        : "r"(a[0]), "r"(a[1]), "r"(a[2]), "r"(a[3]), "r"(b0), "r"(b1));
}
__device__ __forceinline__ void ldsm4(uint32_t* r, uint32_t addr) {
    asm volatile("ldmatrix.sync.aligned.m8n8.x4.shared.b16 {%0,%1,%2,%3}, [%4];"
        : "=r"(r[0]), "=r"(r[1]), "=r"(r[2]), "=r"(r[3]) : "r"(addr));
}
__device__ __forceinline__ void ldsm4t(uint32_t* r, uint32_t addr) {
    asm volatile("ldmatrix.sync.aligned.m8n8.x4.trans.shared.b16 {%0,%1,%2,%3}, [%4];"
        : "=r"(r[0]), "=r"(r[1]), "=r"(r[2]), "=r"(r[3]) : "r"(addr));
}
__device__ __forceinline__ void cpa(uint32_t dst, const void* src) {
    asm volatile("cp.async.cg.shared.global [%0], [%1], 16;" :: "r"(dst), "l"(src));
}
#define CP_COMMIT() asm volatile("cp.async.commit_group;" ::: "memory")
#define CP_WAIT1()  asm volatile("cp.async.wait_group 1;" ::: "memory")
#define CP_WAIT0()  asm volatile("cp.async.wait_group 0;" ::: "memory")

__device__ __forceinline__ void split2(float v, __half& hi, __half& lo) {
    hi = __float2half_rn(v);
    lo = __float2half_rn(v - __half2float(hi));
}
__device__ __forceinline__ uint32_t packh2(float a, float b) {
    __half2 h = __floats2half2_rn(a, b);
    return *(uint32_t*)&h;
}

// ---- prep ----
__global__ __launch_bounds__(256) void split_x_kernel(const float* __restrict__ x) {
    int i = (blockIdx.x * 256 + threadIdx.x) * 4;
    float4 v = *(const float4*)(x + i);
    __half h0,h1,h2,h3,l0,l1,l2,l3;
    split2(v.x,h0,l0); split2(v.y,h1,l1); split2(v.z,h2,l2); split2(v.w,h3,l3);
    __half2 hh[2] = { __halves2half2(h0,h1), __halves2half2(h2,h3) };
    __half2 ll[2] = { __halves2half2(l0,l1), __halves2half2(l2,l3) };
    *(uint2*)(g_xh + i) = *(uint2*)hh;
    *(uint2*)(g_xl + i) = *(uint2*)ll;
}
__global__ __launch_bounds__(256) void wsplit2_kernel(const float* __restrict__ Wa,
                                                      const float* __restrict__ Wb, int widx0) {
    __shared__ float t[32][33];
    const float* W = blockIdx.z ? Wb : Wa;
    int widx = widx0 + blockIdx.z;
    int n0 = blockIdx.x * 32, k0 = blockIdx.y * 32;
    int tx = threadIdx.x, ty = threadIdx.y;
    #pragma unroll
    for (int i = 0; i < 32; i += 8)
        t[ty + i][tx] = W[(size_t)(k0 + ty + i) * DM + n0 + tx];
    __syncthreads();
    #pragma unroll
    for (int i = 0; i < 32; i += 8) {
        int n = n0 + ty + i, k = k0 + tx;
        __half hi, lo; split2(t[tx][ty + i], hi, lo);
        g_wth[widx][(size_t)n * DM + k] = hi;
        g_wtl[widx][(size_t)n * DM + k] = lo;
    }
}

// ---- split-fp16 MMA GEMM (128x128, 2 CTAs/SM, 3-stage) ----
#define GS_BUF  32768
#define G_SMEM  (3*GS_BUF)
#define GS3_BUF 24576
#define G3_SMEM (3*GS3_BUF)
#define NCH     32

__device__ __forceinline__ void g_issue(uint32_t smb, const __half* const* mats,
                                        int c, int tid) {
    if (c < NCH) {
        uint32_t bufb = smb + (c % 3) * GS_BUF;
        #pragma unroll
        for (int i = 0; i < 8; i++) {
            int u = tid + i * 256;
            int mat = u >> 9, rem = u & 511, row = rem >> 2, seg = rem & 3;
            const void* src = mats[mat] + (size_t)row * DM + c * 32 + seg * 8;
            uint32_t dst = bufb + mat * 8192 + row * 64 + ((seg ^ ((row >> 1) & 3)) << 4);
            cpa(dst, src);
        }
    }
    CP_COMMIT();
}

// 3-term: acc += Ah*Bh + Ah*Bl + Al*Bh    (mats = {Ah, Al, Bh, Bl})
__device__ __forceinline__ void g_mainloop(uint32_t smb, const __half* const* mats,
                                           float acc[2][8][4], int tid) {
    const int lane = tid & 31, wid = tid >> 5;
    const int wm = wid >> 1, wn = wid & 1;
    const int rsel = (lane & 7) + ((lane >> 3) & 1) * 8;
    const int chalf = lane >> 4;

    g_issue(smb, mats, 0, tid);
    g_issue(smb, mats, 1, tid);
    for (int c = 0; c < NCH; c++) {
        CP_WAIT1();
        __syncthreads();
        g_issue(smb, mats, c + 2, tid);
        uint32_t ab = smb + (c % 3) * GS_BUF;
        #pragma unroll
        for (int ks = 0; ks < 2; ks++) {
            int sseg = 2 * ks + chalf;
            uint32_t ah[2][4], al_[2][4];
            #pragma unroll
            for (int mi = 0; mi < 2; mi++) {
                int row = wm * 32 + mi * 16 + rsel;
                uint32_t off = row * 64 + ((sseg ^ ((row >> 1) & 3)) << 4);
                ldsm4(ah[mi], ab + off);
                ldsm4(al_[mi], ab + 8192 + off);
            }
            #pragma unroll
            for (int pp = 0; pp < 2; pp++) {
                uint32_t bh_[2][4], bl_[2][4];
                #pragma unroll
                for (int p = 0; p < 2; p++) {
                    int row = wn * 64 + (pp * 2 + p) * 16 + rsel;
                    uint32_t off = row * 64 + ((sseg ^ ((row >> 1) & 3)) << 4);
                    ldsm4(bh_[p], ab + 16384 + off);
                    ldsm4(bl_[p], ab + 24576 + off);
                }
                #pragma unroll
                for (int p = 0; p < 2; p++)
                    #pragma unroll
                    for (int mi = 0; mi < 2; mi++) {
                        int nq = 2 * (2 * pp + p);
                        hmma(acc[mi][nq],     ah[mi], bh_[p][0], bh_[p][2]);
                        hmma(acc[mi][nq + 1], ah[mi], bh_[p][1], bh_[p][3]);
                    }
                #pragma unroll
                for (int p = 0; p < 2; p++)
                    #pragma unroll
                    for (int mi = 0; mi < 2; mi++) {
                        int nq = 2 * (2 * pp + p);
                        hmma(acc[mi][nq],     ah[mi], bl_[p][0], bl_[p][2]);
                        hmma(acc[mi][nq + 1], ah[mi], bl_[p][1], bl_[p][3]);
                    }
                #pragma unroll
                for (int p = 0; p < 2; p++)
                    #pragma unroll
                    for (int mi = 0; mi < 2; mi++) {
                        int nq = 2 * (2 * pp + p);
                        hmma(acc[mi][nq],     al_[mi], bh_[p][0], bh_[p][2]);
                        hmma(acc[mi][nq + 1], al_[mi], bh_[p][1], bh_[p][3]);
                    }
            }
        }
    }
}

// 1-term issue: A hi + B hi only (16KB/chunk, same buffer layout A@0, B@8192)
__device__ __forceinline__ void g_issue1(uint32_t smb, const __half* const* mats,
                                         int c, int tid) {
    if (c < NCH) {
        uint32_t bufb = smb + (c % 3) * GS_BUF;
        #pragma unroll
        for (int i = 0; i < 4; i++) {
            int u = tid + i * 256;
            int mat = u >> 9, rem = u & 511, row = rem >> 2, seg = rem & 3;
            const void* src = mats[mat] + (size_t)row * DM + c * 32 + seg * 8;
            uint32_t dst = bufb + mat * 8192 + row * 64 + ((seg ^ ((row >> 1) & 3)) << 4);
            cpa(dst, src);
        }
    }
    CP_COMMIT();
}

// 1-term: acc += Ah*Bh    (mats = {Ah, Bh})  -- used for V projection
__device__ __forceinline__ void g_mainloop1(uint32_t smb, const __half* const* mats,
                                            float acc[2][8][4], int tid) {
    const int lane = tid & 31, wid = tid >> 5;
    const int wm = wid >> 1, wn = wid & 1;
    const int rsel = (lane & 7) + ((lane >> 3) & 1) * 8;
    const int chalf = lane >> 4;

    g_issue1(smb, mats, 0, tid);
    g_issue1(smb, mats, 1, tid);
    for (int c = 0; c < NCH; c++) {
        CP_WAIT1();
        __syncthreads();
        g_issue1(smb, mats, c + 2, tid);
        uint32_t ab = smb + (c % 3) * GS_BUF;
        #pragma unroll
        for (int ks = 0; ks < 2; ks++) {
            int sseg = 2 * ks + chalf;
            uint32_t ah[2][4];
            #pragma unroll
            for (int mi = 0; mi < 2; mi++) {
                int row = wm * 32 + mi * 16 + rsel;
                uint32_t off = row * 64 + ((sseg ^ ((row >> 1) & 3)) << 4);
                ldsm4(ah[mi], ab + off);
            }
            #pragma unroll
            for (int pp = 0; pp < 2; pp++) {
                uint32_t bh_[2][4];
                #pragma unroll
                for (int p = 0; p < 2; p++) {
                    int row = wn * 64 + (pp * 2 + p) * 16 + rsel;
                    uint32_t off = row * 64 + ((sseg ^ ((row >> 1) & 3)) << 4);
                    ldsm4(bh_[p], ab + 8192 + off);
                }
                #pragma unroll
                for (int p = 0; p < 2; p++)
                    #pragma unroll
                    for (int mi = 0; mi < 2; mi++) {
                        int nq = 2 * (2 * pp + p);
                        hmma(acc[mi][nq],     ah[mi], bh_[p][0], bh_[p][2]);
                        hmma(acc[mi][nq + 1], ah[mi], bh_[p][1], bh_[p][3]);
                    }
            }
        }
    }
}

__device__ __forceinline__ void g_issue3(uint32_t smb, const __half* const* mats,
                                         int c, int tid) {
    if (c < NCH) {
        uint32_t bufb = smb + (c % 3) * GS3_BUF;
        #pragma unroll
        for (int i = 0; i < 6; i++) {
            int u = tid + i * 256;
            int mat = u >> 9, rem = u & 511, row = rem >> 2, seg = rem & 3;
            const void* src = mats[mat] + (size_t)row * DM + c * 32 + seg * 8;
            uint32_t dst = bufb + mat * 8192 + row * 64 + ((seg ^ ((row >> 1) & 3)) << 4);
            cpa(dst, src);
        }
    }
    CP_COMMIT();
}

// 2-term: acc += A*Bh + A*Bl    (mats = {A, Bh, Bl})
__device__ __forceinline__ void g_mainloop3(uint32_t smb, const __half* const* mats,
                                            float acc[2][8][4], int tid) {
    const int lane = tid & 31, wid = tid >> 5;
    const int wm = wid >> 1, wn = wid & 1;
    const int rsel = (lane & 7) + ((lane >> 3) & 1) * 8;
    const int chalf = lane >> 4;

    g_issue3(smb, mats, 0, tid);
    g_issue3(smb, mats, 1, tid);
    for (int c = 0; c < NCH; c++) {
        CP_WAIT1();
        __syncthreads();
        g_issue3(smb, mats, c + 2, tid);
        uint32_t ab = smb + (c % 3) * GS3_BUF;
        #pragma unroll
        for (int ks = 0; ks < 2; ks++) {
            int sseg = 2 * ks + chalf;
            uint32_t ah[2][4];
            #pragma unroll
            for (int mi = 0; mi < 2; mi++) {
                int row = wm * 32 + mi * 16 + rsel;
                uint32_t off = row * 64 + ((sseg ^ ((row >> 1) & 3)) << 4);
                ldsm4(ah[mi], ab + off);
            }
            #pragma unroll
            for (int pp = 0; pp < 2; pp++) {
                uint32_t bh_[2][4], bl_[2][4];
                #pragma unroll
                for (int p = 0; p < 2; p++) {
                    int row = wn * 64 + (pp * 2 + p) * 16 + rsel;
                    uint32_t off = row * 64 + ((sseg ^ ((row >> 1) & 3)) << 4);
                    ldsm4(bh_[p], ab + 8192 + off);
                    ldsm4(bl_[p], ab + 16384 + off);
                }
                #pragma unroll
                for (int p = 0; p < 2; p++)
                    #pragma unroll
                    for (int mi = 0; mi < 2; mi++) {
                        int nq = 2 * (2 * pp + p);
                        hmma(acc[mi][nq],     ah[mi], bh_[p][0], bh_[p][2]);
                        hmma(acc[mi][nq + 1], ah[mi], bh_[p][1], bh_[p][3]);
                    }
                #pragma unroll
                for (int p = 0; p < 2; p++)
                    #pragma unroll
                    for (int mi = 0; mi < 2; mi++) {
                        int nq = 2 * (2 * pp + p);
                        hmma(acc[mi][nq],     ah[mi], bl_[p][0], bl_[p][2]);
                        hmma(acc[mi][nq + 1], ah[mi], bl_[p][1], bl_[p][3]);
                    }
            }
        }
    }
}

// Fused QKV projection: z = 0(Q, 3-term, hi/lo out), 1(K, 3-term, hi/lo out),
//                       z = 2(V, 1-term, hi out)
__global__ __launch_bounds__(256, 2) void qkv_gemm() {
    extern __shared__ char smg[];
    uint32_t smb = smem_u32(smg);
    const int tid = threadIdx.x, lane = tid & 31, wid = tid >> 5;
    const int m0 = blockIdx.y * 128, n0 = blockIdx.x * 128, z = blockIdx.z;
    const int wm = wid >> 1, wn = wid & 1;

    float acc[2][8][4];
    #pragma unroll
    for (int i = 0; i < 2; i++)
        #pragma unroll
        for (int j = 0; j < 8; j++)
            #pragma unroll
            for (int e = 0; e < 4; e++) acc[i][j][e] = 0.f;

    if (z < 2) {
        const __half* mats[4] = { g_xh + (size_t)m0 * DM, g_xl + (size_t)m0 * DM,
                                  g_wth[z] + (size_t)n0 * DM, g_wtl[z] + (size_t)n0 * DM };
        g_mainloop(smb, mats, acc, tid);
    } else {
        const __half* mats[2] = { g_xh + (size_t)m0 * DM, g_wth[2] + (size_t)n0 * DM };
        g_mainloop1(smb, mats, acc, tid);
    }

    __half* Oh = (z == 0) ? g_qh : (z == 1) ? g_kh : g_vh;
    __half* Ol = (z == 0) ? g_ql : g_kl;
    const int g = lane >> 2, q2 = (lane & 3) * 2;
    #pragma unroll
    for (int mi = 0; mi < 2; mi++)
        #pragma unroll
        for (int rr = 0; rr < 2; rr++) {
            int m = m0 + wm * 32 + mi * 16 + g + rr * 8;
            int bb = m >> 11, ss = m & (SEQ - 1);
            #pragma unroll
            for (int nj = 0; nj < 8; nj++) {
                float v0 = acc[mi][nj][rr * 2], v1 = acc[mi][nj][rr * 2 + 1];
                int n = n0 + wn * 64 + nj * 8 + q2;
                int hh = n >> 6, dd = n & 63;
                size_t off = (((size_t)(bb * NH + hh)) * SEQ + ss) * DKV + dd;
                __half h0, h1, l0, l1;
                split2(v0, h0, l0); split2(v1, h1, l1);
                __half2 ph = __halves2half2(h0, h1);
                *(uint32_t*)(Oh + off) = *(uint32_t*)&ph;
                if (z < 2) {
                    __half2 pl = __halves2half2(l0, l1);
                    *(uint32_t*)(Ol + off) = *(uint32_t*)&pl;
                }
            }
        }
}

// Output GEMM: out = ctx_hi @ wo, 2-term (wo hi+lo), fp32 row-major
__global__ __launch_bounds__(256, 2) void out_gemm(float* __restrict__ Cf) {
    extern __shared__ char smg[];
    uint32_t smb = smem_u32(smg);
    const int tid = threadIdx.x, lane = tid & 31, wid = tid >> 5;
    const int m0 = blockIdx.y * 128, n0 = blockIdx.x * 128;
    const int wm = wid >> 1, wn = wid & 1;

    const __half* mats[3] = { g_ch + (size_t)m0 * DM,
                              g_wth[3] + (size_t)n0 * DM, g_wtl[3] + (size_t)n0 * DM };
    float acc[2][8][4];
    #pragma unroll
    for (int i = 0; i < 2; i++)
        #pragma unroll
        for (int j = 0; j < 8; j++)
            #pragma unroll
            for (int e = 0; e < 4; e++) acc[i][j][e] = 0.f;

    g_mainloop3(smb, mats, acc, tid);

    const int g = lane >> 2, q2 = (lane & 3) * 2;
    #pragma unroll
    for (int mi = 0; mi < 2; mi++)
        #pragma unroll
        for (int rr = 0; rr < 2; rr++) {
            int m = m0 + wm * 32 + mi * 16 + g + rr * 8;
            #pragma unroll
            for (int nj = 0; nj < 8; nj++) {
                int n = n0 + wn * 64 + nj * 8 + q2;
                *(float2*)(Cf + (size_t)m * DM + n) =
                    make_float2(acc[mi][nj][rr * 2], acc[mi][nj][rr * 2 + 1]);
            }
        }
}

// ---- FA2-style mma.sync flash attention (R15 version, no stagger) ----
#define AT_QH 0
#define AT_QL 16384
#define AT_KV 32768            /* 2 bufs x 24576 (Kh 8K | Kl 8K | V 8K) */
#define AT_BI 81920
#define AT_SMEM (81920 + 2176*4)

__device__ __forceinline__ void attn_issue(uint32_t smb, const __half* kh, const __half* kl,
                                           const __half* vh, int t, int buf, int tid) {
    #pragma unroll
    for (int i = 0; i < 6; i++) {
        int u = tid + i * 256;
        int mat = u >> 9, rem = u & 511, row = rem >> 3, seg = rem & 7;
        const __half* base = (mat == 0) ? kh : (mat == 1) ? kl : vh;
        const void* src = base + (size_t)(t * 64 + row) * DKV + seg * 8;
        uint32_t dst = smb + AT_KV + buf * 24576 + mat * 8192 + row * 128 + ((seg ^ (row & 7)) << 4);
        cpa(dst, src);
    }
    CP_COMMIT();
}

__global__ __launch_bounds__(256, 2) void attn_mma(const float* __restrict__ rel_emb)
{
    extern __shared__ char smn[];
    uint32_t smb = smem_u32(smn);
    const int tid = threadIdx.x, lane = tid & 31, wid = tid >> 5;
    const int b = blockIdx.z, h = blockIdx.y, q0 = blockIdx.x * 128;
    const size_t hoff = ((size_t)(b * NH + h)) * SEQ * DKV;
    const __half* kh = g_kh + hoff;
    const __half* kl = g_kl + hoff;
    const __half* vh = g_vh + hoff;

    attn_issue(smb, kh, kl, vh, 0, 0, tid);

    #pragma unroll
    for (int i = 0; i < 8; i++) {
        int u = tid + i * 256;
        int mat = u >> 10, rem = u & 1023, row = rem >> 3, seg = rem & 7;
        const uint4* src = (const uint4*)(((mat == 0) ? g_qh : g_ql) + hoff
                             + (size_t)(q0 + row) * DKV + seg * 8);
        *(uint4*)(smn + mat * 16384 + row * 128 + ((seg ^ (row & 7)) << 4)) = *src;
    }
    float* biasS = (float*)(smn + AT_BI);
    for (int j = tid; j < 2175; j += 256) {
        int rel = j - (q0 + 127);
        int n = -rel, ret = 0;
        if (n < 0) { ret = 16; n = -n; }
        int bkt;
        if (n < 8) bkt = n;
        else {
            float t = logf((float)n * 0.125f) / 2.7725887222397812f * 8.0f;
            int v = 8 + (int)t;
            bkt = v < 15 ? v : 15;
        }
        biasS[j] = __ldg(&rel_emb[(ret + bkt) * NH + h]);
    }
    __syncthreads();

    const int rsel = (lane & 7) + ((lane >> 3) & 1) * 8;
    const int chalf = lane >> 4;
    const int qrow = wid * 16 + rsel;

    float O[8][4];
    #pragma unroll
    for (int j = 0; j < 8; j++)
        #pragma unroll
        for (int e = 0; e < 4; e++) O[j][e] = 0.f;
    float m0r = -1e30f, m1r = -1e30f, l0 = 0.f, l1 = 0.f;
    const int g = lane >> 2, q2 = (lane & 3) * 2;
    const int qr0 = wid * 16 + g;

    for (int t = 0; t < 32; t++) {
        CP_WAIT0();
        __syncthreads();
        if (t < 31) attn_issue(smb, kh, kl, vh, t + 1, (t + 1) & 1, tid);
        uint32_t kb = smb + AT_KV + (t & 1) * 24576;

        float s[8][4];
        #pragma unroll
        for (int j = 0; j < 8; j++)
            #pragma unroll
            for (int e = 0; e < 4; e++) s[j][e] = 0.f;

        #pragma unroll
        for (int ks = 0; ks < 4; ks++) {
            int sseg = 2 * ks + chalf;
            uint32_t qfh[4], qfl[4];
            uint32_t qoff = qrow * 128 + ((sseg ^ (qrow & 7)) << 4);
            ldsm4(qfh, smb + AT_QH + qoff);
            ldsm4(qfl, smb + AT_QL + qoff);
            #pragma unroll
            for (int pp = 0; pp < 2; pp++) {
                uint32_t kbh[2][4], kbl[2][4];
                #pragma unroll
                for (int p = 0; p < 2; p++) {
                    int row = (pp * 2 + p) * 16 + rsel;
                    uint32_t off = row * 128 + ((sseg ^ (row & 7)) << 4);
                    ldsm4(kbh[p], kb + off);
                    ldsm4(kbl[p], kb + 8192 + off);
                }
                #pragma unroll
                for (int p = 0; p < 2; p++) {
                    int nq = 2 * (2 * pp + p);
                    hmma(s[nq],     qfh, kbh[p][0], kbh[p][2]);
                    hmma(s[nq + 1], qfh, kbh[p][1], kbh[p][3]);
                }
                #pragma unroll
                for (int p = 0; p < 2; p++) {
                    int nq = 2 * (2 * pp + p);
                    hmma(s[nq],     qfh, kbl[p][0], kbl[p][2]);
                    hmma(s[nq + 1], qfh, kbl[p][1], kbl[p][3]);
                }
                #pragma unroll
                for (int p = 0; p < 2; p++) {
                    int nq = 2 * (2 * pp + p);
                    hmma(s[nq],     qfl, kbh[p][0], kbh[p][2]);
                    hmma(s[nq + 1], qfl, kbh[p][1], kbh[p][3]);
                }
            }
        }

        const float* bp0 = biasS + t * 64 + q2 + 127 - qr0;
        const float* bp1 = bp0 - 8;
        float mx0 = m0r, mx1 = m1r;
        #pragma unroll
        for (int nj = 0; nj < 8; nj++) {
            s[nj][0] += bp0[nj * 8];     s[nj][1] += bp0[nj * 8 + 1];
            s[nj][2] += bp1[nj * 8];     s[nj][3] += bp1[nj * 8 + 1];
            mx0 = fmaxf(mx0, fmaxf(s[nj][0], s[nj][1]));
            mx1 = fmaxf(mx1, fmaxf(s[nj][2], s[nj][3]));
        }
        mx0 = fmaxf(mx0, __shfl_xor_sync(0xffffffffu, mx0, 1));
        mx0 = fmaxf(mx0, __shfl_xor_sync(0xffffffffu, mx0, 2));
        mx1 = fmaxf(mx1, __shfl_xor_sync(0xffffffffu, mx1, 1));
        mx1 = fmaxf(mx1, __shfl_xor_sync(0xffffffffu, mx1, 2));
        float c0 = exp2f((m0r - mx0) * LOG2E);
        float c1 = exp2f((m1r - mx1) * LOG2E);
        m0r = mx0; m1r = mx1;
        float sum0 = 0.f, sum1 = 0.f;
        #pragma unroll
        for (int nj = 0; nj < 8; nj++) {
            s[nj][0] = exp2f((s[nj][0] - mx0) * LOG2E);
            s[nj][1] = exp2f((s[nj][1] - mx0) * LOG2E);
            s[nj][2] = exp2f((s[nj][2] - mx1) * LOG2E);
            s[nj][3] = exp2f((s[nj][3] - mx1) * LOG2E);
            sum0 += s[nj][0] + s[nj][1];
            sum1 += s[nj][2] + s[nj][3];
        }
        sum0 += __shfl_xor_sync(0xffffffffu, sum0, 1);
        sum0 += __shfl_xor_sync(0xffffffffu, sum0, 2);
        sum1 += __shfl_xor_sync(0xffffffffu, sum1, 1);
        sum1 += __shfl_xor_sync(0xffffffffu, sum1, 2);
        l0 = l0 * c0 + sum0;
        l1 = l1 * c1 + sum1;
        #pragma unroll
        for (int nd = 0; nd < 8; nd++) {
            O[nd][0] *= c0; O[nd][1] *= c0; O[nd][2] *= c1; O[nd][3] *= c1;
        }

        #pragma unroll
        for (int kv = 0; kv < 4; kv++) {
            uint32_t pf[4];
            pf[0] = packh2(s[2*kv][0],   s[2*kv][1]);
            pf[1] = packh2(s[2*kv][2],   s[2*kv][3]);
            pf[2] = packh2(s[2*kv+1][0], s[2*kv+1][1]);
            pf[3] = packh2(s[2*kv+1][2], s[2*kv+1][3]);
            int krow = kv * 16 + rsel;
            #pragma unroll
            for (int ndp = 0; ndp < 4; ndp++) {
                int seg = 2 * ndp + chalf;
                uint32_t off = krow * 128 + ((seg ^ (krow & 7)) << 4);
                uint32_t vb[4];
                ldsm4t(vb, kb + 16384 + off);
                hmma(O[2*ndp],   pf, vb[0], vb[1]);
                hmma(O[2*ndp+1], pf, vb[2], vb[3]);
            }
        }
    }

    float inv0 = 1.0f / l0, inv1 = 1.0f / l1;
    #pragma unroll
    for (int rr = 0; rr < 2; rr++) {
        int q = q0 + wid * 16 + g + rr * 8;
        float inv = rr ? inv1 : inv0;
        size_t base = ((size_t)(b * SEQ + q)) * DM + h * DKV + q2;
        #pragma unroll
        for (int nd = 0; nd < 8; nd++) {
            uint32_t ph = packh2(O[nd][rr * 2] * inv, O[nd][rr * 2 + 1] * inv);
            *(uint32_t*)(g_ch + base + nd * 8) = ph;
        }
    }
}

// ---------------------------------------------------------------------------
extern "C" void kernel_launch(void* const* d_in, const int* in_sizes, int n_in,
                              void* d_out, int out_size)
{
    const float* x   = (const float*)d_in[0];
    const float* wq  = (const float*)d_in[1];
    const float* wk  = (const float*)d_in[2];
    const float* wv  = (const float*)d_in[3];
    const float* wo  = (const float*)d_in[4];
    const float* rel = (const float*)d_in[5];
    float* out = (float*)d_out;

    cudaFuncSetAttribute(qkv_gemm, cudaFuncAttributeMaxDynamicSharedMemorySize, G_SMEM);
    cudaFuncSetAttribute(out_gemm, cudaFuncAttributeMaxDynamicSharedMemorySize, G3_SMEM);
    cudaFuncSetAttribute(attn_mma, cudaFuncAttributeMaxDynamicSharedMemorySize, AT_SMEM);

    split_x_kernel<<<MTOT*DM/1024, 256>>>(x);
    dim3 wg(32, 32, 2), wb(32, 8);
    wsplit2_kernel<<<wg, wb>>>(wq, wk, 0);
    wsplit2_kernel<<<wg, wb>>>(wv, wo, 2);
    qkv_gemm<<<dim3(DM/128, MTOT/128, 3), 256, G_SMEM>>>();
    attn_mma<<<dim3(SEQ/128, NH, BATCH), 256, AT_SMEM>>>(rel);
    out_gemm<<<dim3(DM/128, MTOT/128), 256, G3_SMEM>>>(out);
}